// round 15
// baseline (speedup 1.0000x reference)
#include <cuda_runtime.h>
#include <cuda_fp16.h>
#include <math.h>
#include <stdint.h>

// Problem constants
#define BSZ   4096
#define HDIM  300
#define TT    43
#define NCLS  80

// GEMM shapes: m = 2560 weight rows, n = 4096 batch per t
#define MROWS 2560
#define KDIM  320
#define NCOLS 176128
#define MTILES 20
// recurrence
#define NDR   1280
#define KH    320

// staging: 3 stages, KC=64, CTA tile 128(m) x 256(n), fp16
#define KC2    64
#define NCH    5           // 320/64
#define ATB    16384       // A tile: 128 rows * 128 B
#define STG    49152       // A (16K) + B (32K)
#define GS_BYTES (3 * STG) // 147456 -> 1 CTA/SM

#define SW128(o) ((o) ^ (((o) >> 3) & 0x70))

// ---------------- device scratch ----------------------------------------------
__device__ __half g_Wh[(size_t)MROWS * KDIM];          // W_ih fp16 [row'][k]
__device__ __half g_Xh[(size_t)NCOLS * KDIM];          // X fp16 [col=(t*4096+b)][k]
__device__ float  g_zxF[(size_t)TT * 20 * 16 * 32768]; // fragment-order zx
__device__ float  g_bias2560[MROWS];
__device__ __half g_WHh[(size_t)2 * NDR * KH];         // W_hh fp16 [d][row'][k]
__device__ __half g_Hh[(size_t)2 * 2 * BSZ * KH];      // [buf][d][b][k]
__device__ float  g_cF[(size_t)2 * 10 * 16 * 8192];    // fragment-order c
__device__ __half g_hs2[(size_t)BSZ * TT * 2 * KH];    // [b][t][d*320+u]  (fp16)

// ---------------- helpers -------------------------------------------------------
__device__ __forceinline__ float fsig(float x) {
    return __fdividef(1.0f, 1.0f + __expf(-x));
}
__device__ __forceinline__ float ftanh_(float x) {
    float e = __expf(2.0f * x);
    return 1.0f - __fdividef(2.0f, e + 1.0f);
}
__device__ __forceinline__ uint32_t smem_u32(const void* p) {
    uint32_t a;
    asm("{ .reg .u64 t; cvta.to.shared.u64 t, %1; cvt.u32.u64 %0, t; }" : "=r"(a) : "l"(p));
    return a;
}
__device__ __forceinline__ void mma16816(float* c, const uint32_t* a, const uint32_t* b) {
    asm volatile(
        "mma.sync.aligned.m16n8k16.row.col.f32.f16.f16.f32 "
        "{%0,%1,%2,%3}, {%4,%5,%6,%7}, {%8,%9}, {%0,%1,%2,%3};"
        : "+f"(c[0]), "+f"(c[1]), "+f"(c[2]), "+f"(c[3])
        : "r"(a[0]), "r"(a[1]), "r"(a[2]), "r"(a[3]), "r"(b[0]), "r"(b[1]));
}
#define LDSM4(r0, r1, r2, r3, addr)                                               \
    asm volatile("ldmatrix.sync.aligned.m8n8.x4.shared.b16 {%0,%1,%2,%3}, [%4];"  \
                 : "=r"(r0), "=r"(r1), "=r"(r2), "=r"(r3) : "r"(addr))
#define CPA16(dst, src)                                                           \
    asm volatile("cp.async.cg.shared.global [%0], [%1], 16;" :: "r"(dst), "l"(src))
#define CPA_COMMIT() asm volatile("cp.async.commit_group;")
#define CPA_WAIT1()  asm volatile("cp.async.wait_group 1;")
#define CPA_WAIT0()  asm volatile("cp.async.wait_group 0;")

// ---------------- prep kernels --------------------------------------------------
__global__ void prep_wsplit_kernel(const float* __restrict__ wih) {
    int idx = blockIdx.x * blockDim.x + threadIdx.x;
    if (idx >= MROWS * KDIM) return;
    int row = idx / KDIM, k = idx % KDIM;
    int d = row / NDR, r = row % NDR;
    int u = r >> 2, gate = r & 3;
    float v = 0.f;
    if (u < 300 && k < 300)
        v = wih[((size_t)d * 1200 + gate * 300 + u) * 300 + k];
    g_Wh[idx] = __float2half(v);
}

__global__ void prep_whhsplit_kernel(const float* __restrict__ whh) {
    int idx = blockIdx.x * blockDim.x + threadIdx.x;
    if (idx >= 2 * NDR * KH) return;
    int row = idx / KH, k = idx % KH;
    int d = row / NDR, r = row % NDR;
    int u = r >> 2, gate = r & 3;
    float v = 0.f;
    if (u < 300 && k < 300)
        v = whh[((size_t)d * 1200 + gate * 300 + u) * 300 + k];
    g_WHh[idx] = __float2half(v);
}

#define XS_BYTES (300 * 43 * 4)
__global__ void prep_xsplit_kernel(const float* __restrict__ x) {
    extern __shared__ float xs[];
    const int b = blockIdx.x;
    const int tid = threadIdx.x;
    for (int i = tid; i < 300 * TT; i += 256) xs[i] = x[(size_t)b * (300 * TT) + i];
    __syncthreads();
    for (int i = tid; i < TT * KDIM; i += 256) {
        int t = i / KDIM, k = i - t * KDIM;
        float v = (k < 300) ? xs[k * TT + t] : 0.f;
        g_Xh[((size_t)t * BSZ + b) * KDIM + k] = __float2half(v);
    }
}

__global__ void prep_bias_kernel(const float* __restrict__ bih, const float* __restrict__ bhh) {
    int row = blockIdx.x * blockDim.x + threadIdx.x;
    if (row >= MROWS) return;
    int d = row / NDR, r = row % NDR;
    int u = r >> 2, gate = r & 3;
    float v = 0.f;
    if (u < 300)
        v = bih[(size_t)d * 1200 + gate * 300 + u] + bhh[(size_t)d * 1200 + gate * 300 + u];
    g_bias2560[row] = v;
}

__global__ void zero_state_kernel() {
    size_t i = (size_t)blockIdx.x * blockDim.x + threadIdx.x;
    size_t n = (size_t)2 * BSZ * KH;
    if (i >= n) return;
    if (i < (size_t)2 * 10 * 16 * 8192) g_cF[i] = 0.f;
    g_Hh[i] = __float2half(0.f);
}

// ---------------- staging + MMA core ---------------------------------------------
// Stage: A (128 rows) @0, B (256 rows) @ATB; 128B rows, SW128.
#define STAGE_LOAD(ss, kc0, Asrc, Bsrc, aRow0, bRow0, aStride, bStride)                     \
    {                                                                                       \
        uint32_t _sb = smb + (uint32_t)(ss) * STG;                                          \
        _Pragma("unroll")                                                                   \
        for (int it = 0; it < 12; it++) {                                                   \
            if (it < 4) {                                                                   \
                int idx = (it << 8) + tid;                                                  \
                int r = idx >> 3, c8 = idx & 7;                                             \
                uint32_t dst = _sb + SW128((uint32_t)(r * 128 + c8 * 16));                  \
                CPA16(dst, (Asrc) + (size_t)((aRow0) + r) * (aStride) + (kc0) + c8 * 8);    \
            } else {                                                                        \
                int idx = ((it - 4) << 8) + tid;                                            \
                int r = idx >> 3, c8 = idx & 7;                                             \
                uint32_t dst = _sb + ATB + SW128((uint32_t)(r * 128 + c8 * 16));            \
                CPA16(dst, (Bsrc) + (size_t)((bRow0) + r) * (bStride) + (kc0) + c8 * 8);    \
            }                                                                               \
        }                                                                                   \
        CPA_COMMIT();                                                                       \
    }

// per-lane pre-swizzled ldmatrix offsets for the 4 k-slices of a KC=64 chunk
#define LANE_OFFSETS()                                                                      \
    const uint32_t aLin = (uint32_t)(wm * 64 + ((lane >> 3) & 1) * 8 + (lane & 7)) * 128    \
                        + (lane >> 4) * 16;                                                 \
    const uint32_t bLin = (uint32_t)(wn * 64 + (lane >> 4) * 8 + (lane & 7)) * 128          \
                        + ((lane >> 3) & 1) * 16;                                           \
    const uint32_t aOffK[4] = { SW128(aLin), SW128(aLin + 32), SW128(aLin + 64),            \
                                SW128(aLin + 96) };                                         \
    const uint32_t bOffK[4] = { SW128(bLin), SW128(bLin + 32), SW128(bLin + 64),            \
                                SW128(bLin + 96) };

#define MMA_CHUNK(ss)                                                                       \
    {                                                                                       \
        uint32_t _sb = smb + (uint32_t)(ss) * STG;                                          \
        uint32_t bA = _sb, bB = _sb + ATB;                                                  \
        _Pragma("unroll")                                                                   \
        for (int ks = 0; ks < 4; ks++) {                                                    \
            uint32_t aF[4][4], bF[8][2];                                                    \
            _Pragma("unroll")                                                               \
            for (int mt = 0; mt < 4; mt++)                                                  \
                LDSM4(aF[mt][0], aF[mt][1], aF[mt][2], aF[mt][3],                           \
                      bA + aOffK[ks] + mt * 2048);                                          \
            _Pragma("unroll")                                                               \
            for (int pp = 0; pp < 4; pp++)                                                  \
                LDSM4(bF[2 * pp][0], bF[2 * pp][1], bF[2 * pp + 1][0], bF[2 * pp + 1][1],   \
                      bB + bOffK[ks] + pp * 2048);                                          \
            _Pragma("unroll")                                                               \
            for (int mt = 0; mt < 4; mt++)                                                  \
                _Pragma("unroll")                                                           \
                for (int nt = 0; nt < 8; nt++)                                              \
                    mma16816(acc[mt][nt], aF[mt], bF[nt]);                                  \
        }                                                                                   \
    }

// 3-stage mainloop: one barrier per chunk
#define PIPE_LOOP(A_, B_, AR, BR, AS, BS)                                                   \
    for (int chunk = 0; chunk < NCH; chunk++) {                                             \
        if (chunk < NCH - 1) { CPA_WAIT1(); } else { CPA_WAIT0(); }                         \
        __syncthreads();                                                                    \
        if (chunk + 2 < NCH)                                                                \
            STAGE_LOAD(sLoad, (chunk + 2) * KC2, A_, B_, AR, BR, AS, BS);                   \
        MMA_CHUNK(sComp);                                                                   \
        sComp = (sComp == 2) ? 0 : sComp + 1;                                               \
        sLoad = (sLoad == 2) ? 0 : sLoad + 1;                                               \
    }

// ---------------- x-precompute GEMM, one timestep per launch --------------------
__global__ __launch_bounds__(256, 1)
void gemm_zx_kernel(int t) {
    extern __shared__ char sm[];
    const uint32_t smb = smem_u32(sm);
    const int tid  = threadIdx.x;
    const int lane = tid & 31;
    const int wid  = tid >> 5;
    const int wm   = wid & 1;
    const int wn   = wid >> 1;
    const int m0   = blockIdx.x * 128;
    const int btile = blockIdx.y;
    const int n0   = t * BSZ + btile * 256;

    LANE_OFFSETS();

    float acc[4][8][4];
    #pragma unroll
    for (int mt = 0; mt < 4; mt++)
        #pragma unroll
        for (int nt = 0; nt < 8; nt++)
            #pragma unroll
            for (int i = 0; i < 4; i++) acc[mt][nt][i] = 0.f;

    STAGE_LOAD(0, 0,   g_Wh, g_Xh, m0, n0, KDIM, KDIM);
    STAGE_LOAD(1, KC2, g_Wh, g_Xh, m0, n0, KDIM, KDIM);
    int sComp = 0, sLoad = 2;
    PIPE_LOOP(g_Wh, g_Xh, m0, n0, KDIM, KDIM);

    // fragment-order store (+bias)
    float4* zf = (float4*)(g_zxF + (((size_t)t * 20 + blockIdx.x) * 16 + btile) * 32768);
    const int rbase = m0 + wm * 64 + (lane >> 2);
    #pragma unroll
    for (int mt = 0; mt < 4; mt++) {
        int row = rbase + mt * 16;
        float br0 = g_bias2560[row];
        float br8 = g_bias2560[row + 8];
        #pragma unroll
        for (int nt = 0; nt < 8; nt++) {
            float4 v = make_float4(acc[mt][nt][0] + br0, acc[mt][nt][1] + br0,
                                   acc[mt][nt][2] + br8, acc[mt][nt][3] + br8);
            zf[(mt * 8 + nt) * 256 + tid] = v;
        }
    }
}

// ---------------- per-step recurrent GEMM (m=rows, n=batch) ---------------------
__global__ __launch_bounds__(256, 1)
void step_kernel(int t) {
    extern __shared__ char sm[];
    const uint32_t smb = smem_u32(sm);
    const int tid  = threadIdx.x;
    const int lane = tid & 31;
    const int wid  = tid >> 5;
    const int wm   = wid & 1;
    const int wn   = wid >> 1;
    const int mtl   = blockIdx.x;
    const int btile = blockIdx.y;
    const int d     = blockIdx.z;
    const int m0r   = mtl * 128;
    const int n0b   = btile * 256;
    const int p     = t & 1;
    const int q     = 1 - p;

    const __half* WhB = g_WHh + (size_t)d * NDR * KH;
    const __half* HhB = g_Hh + (size_t)(p * 2 + d) * BSZ * KH;

    LANE_OFFSETS();

    STAGE_LOAD(0, 0,   WhB, HhB, m0r, n0b, KH, KH);
    STAGE_LOAD(1, KC2, WhB, HhB, m0r, n0b, KH, KH);

    // init acc from fragment-order zx (overlaps with cp.async staging)
    float acc[4][8][4];
    {
        const float4* zf = (const float4*)(g_zxF +
            (((size_t)t * 20 + (d * 10 + mtl)) * 16 + btile) * 32768);
        #pragma unroll
        for (int mt = 0; mt < 4; mt++)
            #pragma unroll
            for (int nt = 0; nt < 8; nt++) {
                float4 v = zf[(mt * 8 + nt) * 256 + tid];
                acc[mt][nt][0] = v.x; acc[mt][nt][1] = v.y;
                acc[mt][nt][2] = v.z; acc[mt][nt][3] = v.w;
            }
    }

    int sComp = 0, sLoad = 2;
    PIPE_LOOP(WhB, HhB, m0r, n0b, KH, KH);
    __syncthreads();   // all ldmatrix of final chunk done before smem reuse

    // ---- epilogue: 4-lane fragment transpose -> gates -> c update -> hT ----
    const int g = (lane >> 2) & 3;
    float* cS = g_cF + ((size_t)(d * 10 + mtl) * 16 + btile) * 8192;
    float* hT = (float*)sm;   // [256 batch][33]  (33.8 KB, stage reuse)

    #pragma unroll
    for (int mt = 0; mt < 4; mt++) {
        #pragma unroll
        for (int nt = 0; nt < 8; nt++) {
            float v0 = acc[mt][nt][0], v1 = acc[mt][nt][1];
            float v2 = acc[mt][nt][2], v3 = acc[mt][nt][3];
            float a = (g & 2) ? v0 : v2;
            float b = (g & 2) ? v1 : v3;
            a = __shfl_xor_sync(0xffffffffu, a, 8);
            b = __shfl_xor_sync(0xffffffffu, b, 8);
            if (g & 2) { v0 = a; v1 = b; } else { v2 = a; v3 = b; }
            float c01 = (g & 1) ? v0 : v1;
            c01 = __shfl_xor_sync(0xffffffffu, c01, 4);
            if (g & 1) v0 = c01; else v1 = c01;
            float c23 = (g & 1) ? v2 : v3;
            c23 = __shfl_xor_sync(0xffffffffu, c23, 4);
            if (g & 1) v2 = c23; else v3 = c23;
            size_t ci = (size_t)(mt * 8 + nt) * 256 + tid;
            float co = cS[ci];
            float cn = fsig(v1) * co + fsig(v0) * ftanh_(v2);
            cS[ci] = cn;
            float h = fsig(v3) * ftanh_(cn);
            int U = wm * 16 + mt * 4 + ((lane >> 4) & 1) + 2 * (g >> 1);
            int N = wn * 64 + nt * 8 + (lane & 3) * 2 + (g & 1);
            hT[N * 33 + U] = h;
        }
    }
    __syncthreads();

    __half* HhO = g_Hh + (size_t)(q * 2 + d) * BSZ * KH;
    const int U0 = mtl * 32;
    for (int i = tid; i < 256 * 32; i += 256) {
        int bl = i >> 5, ul = i & 31;
        float h = hT[bl * 33 + ul];
        int b = n0b + bl;
        int u = U0 + ul;
        __half hh = __float2half(h);
        HhO[(size_t)b * KH + u] = hh;
        g_hs2[((size_t)b * TT + t) * (2 * KH) + d * KH + u] = hh;
    }
}

// ---------------- attention + FC epilogue ---------------------------------------
#define ATT_SMEM 119856

__global__ __launch_bounds__(256, 1)
void attn_kernel(const float* __restrict__ conv_w,
                 const float* __restrict__ fc_w,
                 const float* __restrict__ fc_b,
                 float* __restrict__ out) {
    extern __shared__ char smem[];
    float* fcT   = (float*)smem;
    float* hstar = (float*)(smem + 96000);
    float* cw    = (float*)(smem + 115200);
    float* e_sh  = cw + 300;
    float* l_sh  = e_sh + 704;
    float* p_sh  = l_sh + 80;

    const int tid = threadIdx.x;
    const int b0  = blockIdx.x * 16;

    for (int i = tid; i < 300; i += 256) cw[i] = conv_w[i];
    for (int i = tid; i < 300 * NCLS; i += 256) {
        int u = i / NCLS, cls = i - u * NCLS;
        fcT[i] = fc_w[(size_t)cls * 300 + u];
    }
    __syncthreads();

    {
        int wid = tid >> 5, lane = tid & 31;
        for (int task = wid; task < 16 * TT; task += 8) {
            int b = task / TT, t = task - b * TT;
            const __half* hp = g_hs2 + ((size_t)(b0 + b) * TT + t) * (2 * KH);
            float s = 0.f;
            for (int u = lane; u < 300; u += 32)
                s += ftanh_(__half2float(hp[u]) + __half2float(hp[KH + u])) * cw[u];
            #pragma unroll
            for (int o = 16; o > 0; o >>= 1) s += __shfl_xor_sync(0xffffffffu, s, o);
            if (lane == 0) e_sh[b * 44 + t] = s;
        }
    }
    __syncthreads();

    if (tid < 16) {
        float m = -1e30f;
        for (int t = 0; t < TT; t++) m = fmaxf(m, e_sh[tid * 44 + t]);
        float ss = 0.f;
        for (int t = 0; t < TT; t++) { float pz = __expf(e_sh[tid * 44 + t] - m); e_sh[tid * 44 + t] = pz; ss += pz; }
        float inv = 1.0f / ss;
        for (int t = 0; t < TT; t++) e_sh[tid * 44 + t] *= inv;
    }
    __syncthreads();

    for (int i = tid; i < 16 * 300; i += 256) {
        int b = i / 300, u = i - b * 300;
        const __half* hp = g_hs2 + ((size_t)(b0 + b) * TT) * (2 * KH) + u;
        float acc = 0.f;
        for (int t = 0; t < TT; t++)
            acc += (__half2float(hp[(size_t)t * (2 * KH)]) +
                    __half2float(hp[(size_t)t * (2 * KH) + KH])) * e_sh[b * 44 + t];
        hstar[i] = ftanh_(acc);
    }
    __syncthreads();

    for (int b = 0; b < 16; b++) {
        if (tid < NCLS) {
            float acc = fc_b[tid];
            const float* hv = hstar + b * 300;
            for (int u = 0; u < 300; u++) acc += hv[u] * fcT[u * NCLS + tid];
            l_sh[tid] = acc;
        }
        __syncthreads();
        if (tid < NCLS) {
            float m = -1e30f;
            for (int j = 0; j < NCLS; j++) m = fmaxf(m, l_sh[j]);
            p_sh[tid] = __expf(l_sh[tid] - m);
        }
        __syncthreads();
        if (tid < NCLS) {
            float s = 0.f;
            for (int j = 0; j < NCLS; j++) s += p_sh[j];
            out[(size_t)(b0 + b) * NCLS + tid] = p_sh[tid] / s;
        }
        __syncthreads();
    }
}

// ---------------- launch ---------------------------------------------------------
extern "C" void kernel_launch(void* const* d_in, const int* in_sizes, int n_in,
                              void* d_out, int out_size) {
    const float* x      = (const float*)d_in[0];
    const float* w_ih   = (const float*)d_in[1];
    const float* w_hh   = (const float*)d_in[2];
    const float* b_ih   = (const float*)d_in[3];
    const float* b_hh   = (const float*)d_in[4];
    const float* conv_w = (const float*)d_in[5];
    const float* fc_w   = (const float*)d_in[6];
    const float* fc_b   = (const float*)d_in[7];
    float* out = (float*)d_out;

    cudaFuncSetAttribute(gemm_zx_kernel,     cudaFuncAttributeMaxDynamicSharedMemorySize, GS_BYTES);
    cudaFuncSetAttribute(step_kernel,        cudaFuncAttributeMaxDynamicSharedMemorySize, GS_BYTES);
    cudaFuncSetAttribute(attn_kernel,        cudaFuncAttributeMaxDynamicSharedMemorySize, ATT_SMEM);
    cudaFuncSetAttribute(prep_xsplit_kernel, cudaFuncAttributeMaxDynamicSharedMemorySize, XS_BYTES);

    cudaStream_t sB;
    cudaStreamCreateWithFlags(&sB, cudaStreamNonBlocking);
    cudaEvent_t evFork, evZx[TT];
    cudaEventCreateWithFlags(&evFork, cudaEventDisableTiming);
    for (int t = 0; t < TT; t++) cudaEventCreateWithFlags(&evZx[t], cudaEventDisableTiming);

    // zx-side preps on the main (captured origin) stream
    prep_wsplit_kernel<<<(MROWS * KDIM + 255) / 256, 256>>>(w_ih);
    prep_xsplit_kernel<<<BSZ, 256, XS_BYTES>>>(x);
    prep_bias_kernel<<<(MROWS + 255) / 256, 256>>>(b_ih, b_hh);

    // fork: zx per-t launches on sB
    cudaEventRecord(evFork, 0);
    cudaStreamWaitEvent(sB, evFork, 0);
    for (int t = 0; t < TT; t++) {
        gemm_zx_kernel<<<dim3(MTILES, 16), 256, GS_BYTES, sB>>>(t);
        cudaEventRecord(evZx[t], sB);
    }

    // step-side preps on the main stream (overlap with early zx work)
    prep_whhsplit_kernel<<<(2 * NDR * KH + 255) / 256, 256>>>(w_hh);
    zero_state_kernel<<<(int)(((size_t)2 * BSZ * KH + 255) / 256), 256>>>();

    // recurrence: step t gated on zx_t
    for (int t = 0; t < TT; t++) {
        cudaStreamWaitEvent(0, evZx[t], 0);
        step_kernel<<<dim3(10, 16, 2), 256, GS_BYTES>>>(t);
    }

    attn_kernel<<<BSZ / 16, 256, ATT_SMEM>>>(conv_w, fc_w, fc_b, out);
}

// round 16
// speedup vs baseline: 1.2170x; 1.2170x over previous
#include <cuda_runtime.h>
#include <cuda_fp16.h>
#include <math.h>
#include <stdint.h>

// Problem constants
#define BSZ   4096
#define HDIM  300
#define TT    43
#define NCLS  80

// GEMM shapes (x-precompute): m = 2560 weight rows, n = 4096 batch per t
#define MROWS 2560
#define KDIM  320
#define NCOLS 176128
#define MTILES 20
// recurrence
#define NDR   1280
#define KH    320

// pipeline staging: 3 stages, KC=64, 128B rows, SW128 swizzle, fp16 single product
#define KC2    64
#define NCH    5           // 320/64
#define TILE16 16384       // 128 rows * 128 B
#define STG    32768       // A + B tiles
#define GS_BYTES (3 * STG) // 98304 -> 2 CTAs/SM

#define SW128(o) ((o) ^ (((o) >> 3) & 0x70))

// ---------------- device scratch ----------------------------------------------
__device__ __half g_Wh[(size_t)MROWS * KDIM];          // W_ih fp16 [row'][k]
__device__ __half g_Xh[(size_t)NCOLS * KDIM];          // X fp16 [col=(t*4096+b)][k]
__device__ float  g_zxF[(size_t)TT * 20 * 32 * 16384]; // fragment-order zx
__device__ float  g_bias2560[MROWS];
__device__ __half g_WHh[(size_t)2 * NDR * KH];         // W_hh fp16 [d][row'][k]
__device__ __half g_Hh[(size_t)2 * 2 * BSZ * KH];      // [buf][d][b][k]
__device__ float  g_cF[(size_t)2 * 10 * 32 * 4096];
__device__ __half g_hs2[(size_t)BSZ * TT * 2 * KH];    // [b][t][d*320+u]  (fp16)

// ---------------- helpers -------------------------------------------------------
__device__ __forceinline__ float fsig(float x) {
    return __fdividef(1.0f, 1.0f + __expf(-x));
}
__device__ __forceinline__ float ftanh_(float x) {
    float e = __expf(2.0f * x);
    return 1.0f - __fdividef(2.0f, e + 1.0f);
}
__device__ __forceinline__ uint32_t smem_u32(const void* p) {
    uint32_t a;
    asm("{ .reg .u64 t; cvta.to.shared.u64 t, %1; cvt.u32.u64 %0, t; }" : "=r"(a) : "l"(p));
    return a;
}
__device__ __forceinline__ void mma16816(float* c, const uint32_t* a, const uint32_t* b) {
    asm volatile(
        "mma.sync.aligned.m16n8k16.row.col.f32.f16.f16.f32 "
        "{%0,%1,%2,%3}, {%4,%5,%6,%7}, {%8,%9}, {%0,%1,%2,%3};"
        : "+f"(c[0]), "+f"(c[1]), "+f"(c[2]), "+f"(c[3])
        : "r"(a[0]), "r"(a[1]), "r"(a[2]), "r"(a[3]), "r"(b[0]), "r"(b[1]));
}
#define LDSM4(r0, r1, r2, r3, addr)                                               \
    asm volatile("ldmatrix.sync.aligned.m8n8.x4.shared.b16 {%0,%1,%2,%3}, [%4];"  \
                 : "=r"(r0), "=r"(r1), "=r"(r2), "=r"(r3) : "r"(addr))
#define CPA16(dst, src)                                                           \
    asm volatile("cp.async.cg.shared.global [%0], [%1], 16;" :: "r"(dst), "l"(src))
#define CPA_COMMIT() asm volatile("cp.async.commit_group;")
#define CPA_WAIT1()  asm volatile("cp.async.wait_group 1;")
#define CPA_WAIT0()  asm volatile("cp.async.wait_group 0;")

// ---------------- prep kernels --------------------------------------------------
__global__ void prep_wsplit_kernel(const float* __restrict__ wih) {
    int idx = blockIdx.x * blockDim.x + threadIdx.x;
    if (idx >= MROWS * KDIM) return;
    int row = idx / KDIM, k = idx % KDIM;
    int d = row / NDR, r = row % NDR;
    int u = r >> 2, gate = r & 3;
    float v = 0.f;
    if (u < 300 && k < 300)
        v = wih[((size_t)d * 1200 + gate * 300 + u) * 300 + k];
    g_Wh[idx] = __float2half(v);
}

__global__ void prep_whhsplit_kernel(const float* __restrict__ whh) {
    int idx = blockIdx.x * blockDim.x + threadIdx.x;
    if (idx >= 2 * NDR * KH) return;
    int row = idx / KH, k = idx % KH;
    int d = row / NDR, r = row % NDR;
    int u = r >> 2, gate = r & 3;
    float v = 0.f;
    if (u < 300 && k < 300)
        v = whh[((size_t)d * 1200 + gate * 300 + u) * 300 + k];
    g_WHh[idx] = __float2half(v);
}

#define XS_BYTES (300 * 43 * 4)
__global__ void prep_xsplit_kernel(const float* __restrict__ x) {
    extern __shared__ float xs[];
    const int b = blockIdx.x;
    const int tid = threadIdx.x;
    for (int i = tid; i < 300 * TT; i += 256) xs[i] = x[(size_t)b * (300 * TT) + i];
    __syncthreads();
    for (int i = tid; i < TT * KDIM; i += 256) {
        int t = i / KDIM, k = i - t * KDIM;
        float v = (k < 300) ? xs[k * TT + t] : 0.f;
        g_Xh[((size_t)t * BSZ + b) * KDIM + k] = __float2half(v);
    }
}

__global__ void prep_bias_kernel(const float* __restrict__ bih, const float* __restrict__ bhh) {
    int row = blockIdx.x * blockDim.x + threadIdx.x;
    if (row >= MROWS) return;
    int d = row / NDR, r = row % NDR;
    int u = r >> 2, gate = r & 3;
    float v = 0.f;
    if (u < 300)
        v = bih[(size_t)d * 1200 + gate * 300 + u] + bhh[(size_t)d * 1200 + gate * 300 + u];
    g_bias2560[row] = v;
}

__global__ void zero_state_kernel() {
    size_t i = (size_t)blockIdx.x * blockDim.x + threadIdx.x;
    size_t n = (size_t)2 * BSZ * KH;
    if (i >= n) return;
    g_cF[i] = 0.f;
    g_Hh[i] = __float2half(0.f);
}

// ---------------- staging + MMA core ---------------------------------------------
// Stage: A @0, B @TILE16; 128B rows, SW128 swizzle.
#define STAGE_LOAD(ss, kc0, Asrc, Bsrc, aRow0, bRow0, aStride, bStride)                     \
    {                                                                                       \
        uint32_t _sb = smb + (uint32_t)(ss) * STG;                                          \
        _Pragma("unroll")                                                                   \
        for (int it = 0; it < 8; it++) {                                                    \
            int idx = ((it & 3) << 8) + tid;                                                \
            int r = idx >> 3, c8 = idx & 7;                                                 \
            uint32_t dst = _sb + (it >> 2) * TILE16 + SW128((uint32_t)(r * 128 + c8 * 16)); \
            const __half* src = ((it >> 2) == 0)                                            \
                ? (Asrc) + (size_t)((aRow0) + r) * (aStride) + (kc0) + c8 * 8               \
                : (Bsrc) + (size_t)((bRow0) + r) * (bStride) + (kc0) + c8 * 8;              \
            CPA16(dst, src);                                                                \
        }                                                                                   \
        CPA_COMMIT();                                                                       \
    }

// per-lane pre-swizzled ldmatrix offsets for the 4 k-slices of a KC=64 chunk
#define LANE_OFFSETS()                                                                      \
    const uint32_t aLin = (uint32_t)(wm * 64 + ((lane >> 3) & 1) * 8 + (lane & 7)) * 128    \
                        + (lane >> 4) * 16;                                                 \
    const uint32_t bLin = (uint32_t)(wn * 32 + (lane >> 4) * 8 + (lane & 7)) * 128          \
                        + ((lane >> 3) & 1) * 16;                                           \
    const uint32_t aOffK[4] = { SW128(aLin), SW128(aLin + 32), SW128(aLin + 64),            \
                                SW128(aLin + 96) };                                         \
    const uint32_t bOffK[4] = { SW128(bLin), SW128(bLin + 32), SW128(bLin + 64),            \
                                SW128(bLin + 96) };

#define MMA_CHUNK(ss)                                                                       \
    {                                                                                       \
        uint32_t _sb = smb + (uint32_t)(ss) * STG;                                          \
        uint32_t bA = _sb, bB = _sb + TILE16;                                               \
        _Pragma("unroll")                                                                   \
        for (int ks = 0; ks < 4; ks++) {                                                    \
            uint32_t aF[4][4], bF[4][2];                                                    \
            _Pragma("unroll")                                                               \
            for (int mt = 0; mt < 4; mt++)                                                  \
                LDSM4(aF[mt][0], aF[mt][1], aF[mt][2], aF[mt][3],                           \
                      bA + aOffK[ks] + mt * 2048);                                          \
            _Pragma("unroll")                                                               \
            for (int pp = 0; pp < 2; pp++)                                                  \
                LDSM4(bF[2 * pp][0], bF[2 * pp][1], bF[2 * pp + 1][0], bF[2 * pp + 1][1],   \
                      bB + bOffK[ks] + pp * 2048);                                          \
            _Pragma("unroll")                                                               \
            for (int mt = 0; mt < 4; mt++)                                                  \
                _Pragma("unroll")                                                           \
                for (int nt = 0; nt < 4; nt++)                                              \
                    mma16816(acc[mt][nt], aF[mt], bF[nt]);                                  \
        }                                                                                   \
    }

// 3-stage mainloop: one barrier per chunk
#define PIPE_LOOP(A_, B_, AR, BR, AS, BS)                                                   \
    for (int chunk = 0; chunk < NCH; chunk++) {                                             \
        if (chunk < NCH - 1) { CPA_WAIT1(); } else { CPA_WAIT0(); }                         \
        __syncthreads();                                                                    \
        if (chunk + 2 < NCH)                                                                \
            STAGE_LOAD(sLoad, (chunk + 2) * KC2, A_, B_, AR, BR, AS, BS);                   \
        MMA_CHUNK(sComp);                                                                   \
        sComp = (sComp == 2) ? 0 : sComp + 1;                                               \
        sLoad = (sLoad == 2) ? 0 : sLoad + 1;                                               \
    }

// ---------------- x-precompute GEMM, one timestep per launch --------------------
__global__ __launch_bounds__(256, 2)
void gemm_zx_kernel(int t) {
    extern __shared__ char sm[];
    const uint32_t smb = smem_u32(sm);
    const int tid  = threadIdx.x;
    const int lane = tid & 31;
    const int wid  = tid >> 5;
    const int wm   = wid & 1;
    const int wn   = wid >> 1;
    const int m0   = blockIdx.x * 128;
    const int btile = blockIdx.y;
    const int n0   = t * BSZ + btile * 128;

    LANE_OFFSETS();

    float acc[4][4][4];
    #pragma unroll
    for (int mt = 0; mt < 4; mt++)
        #pragma unroll
        for (int nt = 0; nt < 4; nt++)
            #pragma unroll
            for (int i = 0; i < 4; i++) acc[mt][nt][i] = 0.f;

    STAGE_LOAD(0, 0,   g_Wh, g_Xh, m0, n0, KDIM, KDIM);
    STAGE_LOAD(1, KC2, g_Wh, g_Xh, m0, n0, KDIM, KDIM);
    int sComp = 0, sLoad = 2;
    PIPE_LOOP(g_Wh, g_Xh, m0, n0, KDIM, KDIM);

    // fragment-order store (+bias)
    float4* zf = (float4*)(g_zxF + (((size_t)t * 20 + blockIdx.x) * 32 + btile) * 16384);
    const int rbase = m0 + wm * 64 + (lane >> 2);
    #pragma unroll
    for (int mt = 0; mt < 4; mt++) {
        int row = rbase + mt * 16;
        float br0 = g_bias2560[row];
        float br8 = g_bias2560[row + 8];
        #pragma unroll
        for (int nt = 0; nt < 4; nt++) {
            float4 v = make_float4(acc[mt][nt][0] + br0, acc[mt][nt][1] + br0,
                                   acc[mt][nt][2] + br8, acc[mt][nt][3] + br8);
            zf[(mt * 4 + nt) * 256 + tid] = v;
        }
    }
}

// ---------------- per-step recurrent GEMM (m=rows, n=batch) ---------------------
__global__ __launch_bounds__(256, 2)
void step_kernel(int t) {
    extern __shared__ char sm[];
    const uint32_t smb = smem_u32(sm);
    const int tid  = threadIdx.x;
    const int lane = tid & 31;
    const int wid  = tid >> 5;
    const int wm   = wid & 1;
    const int wn   = wid >> 1;
    const int mtl   = blockIdx.x;
    const int btile = blockIdx.y;
    const int d     = blockIdx.z;
    const int m0r   = mtl * 128;
    const int n0b   = btile * 128;
    const int p     = t & 1;
    const int q     = 1 - p;

    const __half* WhB = g_WHh + (size_t)d * NDR * KH;
    const __half* HhB = g_Hh + (size_t)(p * 2 + d) * BSZ * KH;

    LANE_OFFSETS();

    STAGE_LOAD(0, 0,   WhB, HhB, m0r, n0b, KH, KH);
    STAGE_LOAD(1, KC2, WhB, HhB, m0r, n0b, KH, KH);

    // init acc from fragment-order zx (overlaps with cp.async staging)
    float acc[4][4][4];
    {
        const float4* zf = (const float4*)(g_zxF +
            (((size_t)t * 20 + (d * 10 + mtl)) * 32 + btile) * 16384);
        #pragma unroll
        for (int mt = 0; mt < 4; mt++)
            #pragma unroll
            for (int nt = 0; nt < 4; nt++) {
                float4 v = zf[(mt * 4 + nt) * 256 + tid];
                acc[mt][nt][0] = v.x; acc[mt][nt][1] = v.y;
                acc[mt][nt][2] = v.z; acc[mt][nt][3] = v.w;
            }
    }

    int sComp = 0, sLoad = 2;
    PIPE_LOOP(WhB, HhB, m0r, n0b, KH, KH);
    __syncthreads();   // all ldmatrix of final chunk done before smem reuse

    // ---- epilogue: 4-lane fragment transpose -> gates -> c update -> hT ----
    const int g = (lane >> 2) & 3;
    float* cS = g_cF + ((size_t)(d * 10 + mtl) * 32 + btile) * 4096;
    float* hT = (float*)sm;   // [128 batch][33]

    #pragma unroll
    for (int mt = 0; mt < 4; mt++) {
        #pragma unroll
        for (int nt = 0; nt < 4; nt++) {
            float v0 = acc[mt][nt][0], v1 = acc[mt][nt][1];
            float v2 = acc[mt][nt][2], v3 = acc[mt][nt][3];
            float a = (g & 2) ? v0 : v2;
            float b = (g & 2) ? v1 : v3;
            a = __shfl_xor_sync(0xffffffffu, a, 8);
            b = __shfl_xor_sync(0xffffffffu, b, 8);
            if (g & 2) { v0 = a; v1 = b; } else { v2 = a; v3 = b; }
            float c01 = (g & 1) ? v0 : v1;
            c01 = __shfl_xor_sync(0xffffffffu, c01, 4);
            if (g & 1) v0 = c01; else v1 = c01;
            float c23 = (g & 1) ? v2 : v3;
            c23 = __shfl_xor_sync(0xffffffffu, c23, 4);
            if (g & 1) v2 = c23; else v3 = c23;
            size_t ci = (size_t)(mt * 4 + nt) * 256 + tid;
            float co = cS[ci];
            float cn = fsig(v1) * co + fsig(v0) * ftanh_(v2);
            cS[ci] = cn;
            float h = fsig(v3) * ftanh_(cn);
            int U = wm * 16 + mt * 4 + ((lane >> 4) & 1) + 2 * (g >> 1);
            int N = wn * 32 + nt * 8 + (lane & 3) * 2 + (g & 1);
            hT[N * 33 + U] = h;
        }
    }
    __syncthreads();

    __half* HhO = g_Hh + (size_t)(q * 2 + d) * BSZ * KH;
    const int U0 = mtl * 32;
    for (int i = tid; i < 128 * 32; i += 256) {
        int bl = i >> 5, ul = i & 31;
        float h = hT[bl * 33 + ul];
        int b = n0b + bl;
        int u = U0 + ul;
        __half hh = __float2half(h);
        HhO[(size_t)b * KH + u] = hh;
        g_hs2[((size_t)b * TT + t) * (2 * KH) + d * KH + u] = hh;
    }
}

// ---------------- attention + FC epilogue ---------------------------------------
#define ATT_SMEM 119856

__global__ __launch_bounds__(256, 1)
void attn_kernel(const float* __restrict__ conv_w,
                 const float* __restrict__ fc_w,
                 const float* __restrict__ fc_b,
                 float* __restrict__ out) {
    extern __shared__ char smem[];
    float* fcT   = (float*)smem;
    float* hstar = (float*)(smem + 96000);
    float* cw    = (float*)(smem + 115200);
    float* e_sh  = cw + 300;
    float* l_sh  = e_sh + 704;
    float* p_sh  = l_sh + 80;

    const int tid = threadIdx.x;
    const int b0  = blockIdx.x * 16;

    for (int i = tid; i < 300; i += 256) cw[i] = conv_w[i];
    for (int i = tid; i < 300 * NCLS; i += 256) {
        int u = i / NCLS, cls = i - u * NCLS;
        fcT[i] = fc_w[(size_t)cls * 300 + u];
    }
    __syncthreads();

    {
        int wid = tid >> 5, lane = tid & 31;
        for (int task = wid; task < 16 * TT; task += 8) {
            int b = task / TT, t = task - b * TT;
            const __half* hp = g_hs2 + ((size_t)(b0 + b) * TT + t) * (2 * KH);
            float s = 0.f;
            for (int u = lane; u < 300; u += 32)
                s += ftanh_(__half2float(hp[u]) + __half2float(hp[KH + u])) * cw[u];
            #pragma unroll
            for (int o = 16; o > 0; o >>= 1) s += __shfl_xor_sync(0xffffffffu, s, o);
            if (lane == 0) e_sh[b * 44 + t] = s;
        }
    }
    __syncthreads();

    if (tid < 16) {
        float m = -1e30f;
        for (int t = 0; t < TT; t++) m = fmaxf(m, e_sh[tid * 44 + t]);
        float ss = 0.f;
        for (int t = 0; t < TT; t++) { float pz = __expf(e_sh[tid * 44 + t] - m); e_sh[tid * 44 + t] = pz; ss += pz; }
        float inv = 1.0f / ss;
        for (int t = 0; t < TT; t++) e_sh[tid * 44 + t] *= inv;
    }
    __syncthreads();

    for (int i = tid; i < 16 * 300; i += 256) {
        int b = i / 300, u = i - b * 300;
        const __half* hp = g_hs2 + ((size_t)(b0 + b) * TT) * (2 * KH) + u;
        float acc = 0.f;
        for (int t = 0; t < TT; t++)
            acc += (__half2float(hp[(size_t)t * (2 * KH)]) +
                    __half2float(hp[(size_t)t * (2 * KH) + KH])) * e_sh[b * 44 + t];
        hstar[i] = ftanh_(acc);
    }
    __syncthreads();

    for (int b = 0; b < 16; b++) {
        if (tid < NCLS) {
            float acc = fc_b[tid];
            const float* hv = hstar + b * 300;
            for (int u = 0; u < 300; u++) acc += hv[u] * fcT[u * NCLS + tid];
            l_sh[tid] = acc;
        }
        __syncthreads();
        if (tid < NCLS) {
            float m = -1e30f;
            for (int j = 0; j < NCLS; j++) m = fmaxf(m, l_sh[j]);
            p_sh[tid] = __expf(l_sh[tid] - m);
        }
        __syncthreads();
        if (tid < NCLS) {
            float s = 0.f;
            for (int j = 0; j < NCLS; j++) s += p_sh[j];
            out[(size_t)(b0 + b) * NCLS + tid] = p_sh[tid] / s;
        }
        __syncthreads();
    }
}

// ---------------- launch ---------------------------------------------------------
extern "C" void kernel_launch(void* const* d_in, const int* in_sizes, int n_in,
                              void* d_out, int out_size) {
    const float* x      = (const float*)d_in[0];
    const float* w_ih   = (const float*)d_in[1];
    const float* w_hh   = (const float*)d_in[2];
    const float* b_ih   = (const float*)d_in[3];
    const float* b_hh   = (const float*)d_in[4];
    const float* conv_w = (const float*)d_in[5];
    const float* fc_w   = (const float*)d_in[6];
    const float* fc_b   = (const float*)d_in[7];
    float* out = (float*)d_out;

    cudaFuncSetAttribute(gemm_zx_kernel,     cudaFuncAttributeMaxDynamicSharedMemorySize, GS_BYTES);
    cudaFuncSetAttribute(step_kernel,        cudaFuncAttributeMaxDynamicSharedMemorySize, GS_BYTES);
    cudaFuncSetAttribute(attn_kernel,        cudaFuncAttributeMaxDynamicSharedMemorySize, ATT_SMEM);
    cudaFuncSetAttribute(prep_xsplit_kernel, cudaFuncAttributeMaxDynamicSharedMemorySize, XS_BYTES);

    cudaStream_t sB;
    cudaStreamCreateWithFlags(&sB, cudaStreamNonBlocking);
    cudaEvent_t evFork, evZx[TT];
    cudaEventCreateWithFlags(&evFork, cudaEventDisableTiming);
    for (int t = 0; t < TT; t++) cudaEventCreateWithFlags(&evZx[t], cudaEventDisableTiming);

    // zx-side preps on the main (captured origin) stream
    prep_wsplit_kernel<<<(MROWS * KDIM + 255) / 256, 256>>>(w_ih);
    prep_xsplit_kernel<<<BSZ, 256, XS_BYTES>>>(x);
    prep_bias_kernel<<<(MROWS + 255) / 256, 256>>>(b_ih, b_hh);

    // fork: zx per-t launches on sB
    cudaEventRecord(evFork, 0);
    cudaStreamWaitEvent(sB, evFork, 0);
    for (int t = 0; t < TT; t++) {
        gemm_zx_kernel<<<dim3(MTILES, 32), 256, GS_BYTES, sB>>>(t);
        cudaEventRecord(evZx[t], sB);
    }

    // step-side preps on the main stream (overlap with early zx work)
    prep_whhsplit_kernel<<<(2 * NDR * KH + 255) / 256, 256>>>(w_hh);
    zero_state_kernel<<<(int)(((size_t)2 * BSZ * KH + 255) / 256), 256>>>();

    // recurrence: step t gated on zx_t
    for (int t = 0; t < TT; t++) {
        cudaStreamWaitEvent(0, evZx[t], 0);
        step_kernel<<<dim3(10, 32, 2), 256, GS_BYTES>>>(t);
    }

    attn_kernel<<<BSZ / 16, 256, ATT_SMEM>>>(conv_w, fc_w, fc_b, out);
}

// round 17
// speedup vs baseline: 1.3009x; 1.0689x over previous
#include <cuda_runtime.h>
#include <cuda_fp16.h>
#include <math.h>
#include <stdint.h>

// Problem constants
#define BSZ   4096
#define HDIM  300
#define TT    43
#define NCLS  80

// GEMM shapes (x-precompute): m = 2560 weight rows, n = 4096 batch per t
#define MROWS 2560
#define KDIM  320
#define NCOLS 176128
#define MTILES 20
// recurrence
#define NDR   1280
#define KH    320

// pipeline staging: 3 stages, KC=64, 128B rows, SW128 swizzle, fp16 single product
#define KC2    64
#define NCH    5           // 320/64
#define TILE16 16384       // 128 rows * 128 B
#define STG    32768       // A + B tiles
#define GS_BYTES (3 * STG) // 98304 -> 2 CTAs/SM

#define SW128(o) ((o) ^ (((o) >> 3) & 0x70))

// ---------------- device scratch ----------------------------------------------
__device__ __half g_Wh[(size_t)MROWS * KDIM];          // W_ih fp16 [row'][k]
__device__ __half g_Xh[(size_t)NCOLS * KDIM];          // X fp16 [col=(t*4096+b)][k]
__device__ float  g_zxF[(size_t)TT * 20 * 32 * 16384]; // fragment-order zx
__device__ float  g_bias2560[MROWS];
__device__ __half g_WHh[(size_t)2 * NDR * KH];         // W_hh fp16 [d][row'][k]
__device__ __half g_Hh[(size_t)2 * 2 * BSZ * KH];      // [buf][d][b][k]
__device__ float  g_cF[(size_t)2 * 10 * 32 * 4096];
__device__ __half g_hs2[(size_t)BSZ * TT * 2 * KH];    // [b][t][d*320+u]  (fp16)

// ---------------- helpers -------------------------------------------------------
__device__ __forceinline__ float fsig(float x) {
    return __fdividef(1.0f, 1.0f + __expf(-x));
}
__device__ __forceinline__ float ftanh_(float x) {
    float e = __expf(2.0f * x);
    return 1.0f - __fdividef(2.0f, e + 1.0f);
}
__device__ __forceinline__ uint32_t smem_u32(const void* p) {
    uint32_t a;
    asm("{ .reg .u64 t; cvta.to.shared.u64 t, %1; cvt.u32.u64 %0, t; }" : "=r"(a) : "l"(p));
    return a;
}
__device__ __forceinline__ void mma16816(float* c, const uint32_t* a, const uint32_t* b) {
    asm volatile(
        "mma.sync.aligned.m16n8k16.row.col.f32.f16.f16.f32 "
        "{%0,%1,%2,%3}, {%4,%5,%6,%7}, {%8,%9}, {%0,%1,%2,%3};"
        : "+f"(c[0]), "+f"(c[1]), "+f"(c[2]), "+f"(c[3])
        : "r"(a[0]), "r"(a[1]), "r"(a[2]), "r"(a[3]), "r"(b[0]), "r"(b[1]));
}
#define LDSM4(r0, r1, r2, r3, addr)                                               \
    asm volatile("ldmatrix.sync.aligned.m8n8.x4.shared.b16 {%0,%1,%2,%3}, [%4];"  \
                 : "=r"(r0), "=r"(r1), "=r"(r2), "=r"(r3) : "r"(addr))
#define CPA16(dst, src)                                                           \
    asm volatile("cp.async.cg.shared.global [%0], [%1], 16;" :: "r"(dst), "l"(src))
#define CPA_COMMIT() asm volatile("cp.async.commit_group;")
#define CPA_WAIT1()  asm volatile("cp.async.wait_group 1;")
#define CPA_WAIT0()  asm volatile("cp.async.wait_group 0;")

// ---------------- prep kernels --------------------------------------------------
__global__ void prep_wsplit_kernel(const float* __restrict__ wih) {
    int idx = blockIdx.x * blockDim.x + threadIdx.x;
    if (idx >= MROWS * KDIM) return;
    int row = idx / KDIM, k = idx % KDIM;
    int d = row / NDR, r = row % NDR;
    int u = r >> 2, gate = r & 3;
    float v = 0.f;
    if (u < 300 && k < 300)
        v = wih[((size_t)d * 1200 + gate * 300 + u) * 300 + k];
    g_Wh[idx] = __float2half(v);
}

__global__ void prep_whhsplit_kernel(const float* __restrict__ whh) {
    int idx = blockIdx.x * blockDim.x + threadIdx.x;
    if (idx >= 2 * NDR * KH) return;
    int row = idx / KH, k = idx % KH;
    int d = row / NDR, r = row % NDR;
    int u = r >> 2, gate = r & 3;
    float v = 0.f;
    if (u < 300 && k < 300)
        v = whh[((size_t)d * 1200 + gate * 300 + u) * 300 + k];
    g_WHh[idx] = __float2half(v);
}

#define XS_BYTES (300 * 43 * 4)
__global__ void prep_xsplit_kernel(const float* __restrict__ x) {
    extern __shared__ float xs[];
    const int b = blockIdx.x;
    const int tid = threadIdx.x;
    for (int i = tid; i < 300 * TT; i += 256) xs[i] = x[(size_t)b * (300 * TT) + i];
    __syncthreads();
    for (int i = tid; i < TT * KDIM; i += 256) {
        int t = i / KDIM, k = i - t * KDIM;
        float v = (k < 300) ? xs[k * TT + t] : 0.f;
        g_Xh[((size_t)t * BSZ + b) * KDIM + k] = __float2half(v);
    }
}

__global__ void prep_bias_kernel(const float* __restrict__ bih, const float* __restrict__ bhh) {
    int row = blockIdx.x * blockDim.x + threadIdx.x;
    if (row >= MROWS) return;
    int d = row / NDR, r = row % NDR;
    int u = r >> 2, gate = r & 3;
    float v = 0.f;
    if (u < 300)
        v = bih[(size_t)d * 1200 + gate * 300 + u] + bhh[(size_t)d * 1200 + gate * 300 + u];
    g_bias2560[row] = v;
}

__global__ void zero_state_kernel() {
    size_t i = (size_t)blockIdx.x * blockDim.x + threadIdx.x;
    size_t n = (size_t)2 * BSZ * KH;
    if (i >= n) return;
    g_cF[i] = 0.f;
    g_Hh[i] = __float2half(0.f);
}

// ---------------- staging + MMA core ---------------------------------------------
// Stage: A @0, B @TILE16; 128B rows, SW128 swizzle.
#define STAGE_LOAD(ss, kc0, Asrc, Bsrc, aRow0, bRow0, aStride, bStride)                     \
    {                                                                                       \
        uint32_t _sb = smb + (uint32_t)(ss) * STG;                                          \
        _Pragma("unroll")                                                                   \
        for (int it = 0; it < 8; it++) {                                                    \
            int idx = ((it & 3) << 8) + tid;                                                \
            int r = idx >> 3, c8 = idx & 7;                                                 \
            uint32_t dst = _sb + (it >> 2) * TILE16 + SW128((uint32_t)(r * 128 + c8 * 16)); \
            const __half* src = ((it >> 2) == 0)                                            \
                ? (Asrc) + (size_t)((aRow0) + r) * (aStride) + (kc0) + c8 * 8               \
                : (Bsrc) + (size_t)((bRow0) + r) * (bStride) + (kc0) + c8 * 8;              \
            CPA16(dst, src);                                                                \
        }                                                                                   \
        CPA_COMMIT();                                                                       \
    }

// per-lane linear ldmatrix base offsets (swizzle applied per-ks arithmetically)
#define LANE_OFFSETS()                                                                      \
    const uint32_t aLin = (uint32_t)(wm * 64 + ((lane >> 3) & 1) * 8 + (lane & 7)) * 128    \
                        + (lane >> 4) * 16;                                                 \
    const uint32_t bLin = (uint32_t)(wn * 32 + (lane >> 4) * 8 + (lane & 7)) * 128          \
                        + ((lane >> 3) & 1) * 16;

// MMA over one staged chunk; KSN k-slices, warp-rotated start phase PH.
#define MMA_CHUNK(ss, KSN, PH)                                                              \
    {                                                                                       \
        uint32_t _sb = smb + (uint32_t)(ss) * STG;                                          \
        uint32_t bA = _sb, bB = _sb + TILE16;                                               \
        _Pragma("unroll")                                                                   \
        for (int kk = 0; kk < (KSN); kk++) {                                                \
            int ks = kk + (PH); if (ks >= (KSN)) ks -= (KSN);                               \
            uint32_t aL2 = aLin + (uint32_t)ks * 32;                                        \
            uint32_t bL2 = bLin + (uint32_t)ks * 32;                                        \
            uint32_t aOff = SW128(aL2);                                                     \
            uint32_t bOff = SW128(bL2);                                                     \
            uint32_t aF[4][4], bF[4][2];                                                    \
            _Pragma("unroll")                                                               \
            for (int mt = 0; mt < 4; mt++)                                                  \
                LDSM4(aF[mt][0], aF[mt][1], aF[mt][2], aF[mt][3],                           \
                      bA + aOff + mt * 2048);                                               \
            _Pragma("unroll")                                                               \
            for (int pp = 0; pp < 2; pp++)                                                  \
                LDSM4(bF[2 * pp][0], bF[2 * pp][1], bF[2 * pp + 1][0], bF[2 * pp + 1][1],   \
                      bB + bOff + pp * 2048);                                               \
            _Pragma("unroll")                                                               \
            for (int mt = 0; mt < 4; mt++)                                                  \
                _Pragma("unroll")                                                           \
                for (int nt = 0; nt < 4; nt++)                                              \
                    mma16816(acc[mt][nt], aF[mt], bF[nt]);                                  \
        }                                                                                   \
    }

// 3-stage mainloop: one barrier per chunk; last chunk skips the all-zero k-slice
#define PIPE_LOOP(A_, B_, AR, BR, AS, BS)                                                   \
    {                                                                                       \
        const int ph4 = wid & 3;                                                            \
        const int ph3 = wid % 3;                                                            \
        _Pragma("unroll")                                                                   \
        for (int chunk = 0; chunk < NCH; chunk++) {                                         \
            if (chunk < NCH - 1) { CPA_WAIT1(); } else { CPA_WAIT0(); }                     \
            __syncthreads();                                                                \
            if (chunk + 2 < NCH)                                                            \
                STAGE_LOAD(sLoad, (chunk + 2) * KC2, A_, B_, AR, BR, AS, BS);               \
            if (chunk < NCH - 1) {                                                          \
                MMA_CHUNK(sComp, 4, ph4);                                                   \
            } else {                                                                        \
                MMA_CHUNK(sComp, 3, ph3);   /* k 304..319 is zero padding */                \
            }                                                                               \
            sComp = (sComp == 2) ? 0 : sComp + 1;                                           \
            sLoad = (sLoad == 2) ? 0 : sLoad + 1;                                           \
        }                                                                                   \
    }

// ---------------- x-precompute GEMM, one timestep per launch --------------------
__global__ __launch_bounds__(256, 2)
void gemm_zx_kernel(int t) {
    extern __shared__ char sm[];
    const uint32_t smb = smem_u32(sm);
    const int tid  = threadIdx.x;
    const int lane = tid & 31;
    const int wid  = tid >> 5;
    const int wm   = wid & 1;
    const int wn   = wid >> 1;
    const int m0   = blockIdx.x * 128;
    const int btile = blockIdx.y;
    const int n0   = t * BSZ + btile * 128;

    LANE_OFFSETS();

    float acc[4][4][4];
    #pragma unroll
    for (int mt = 0; mt < 4; mt++)
        #pragma unroll
        for (int nt = 0; nt < 4; nt++)
            #pragma unroll
            for (int i = 0; i < 4; i++) acc[mt][nt][i] = 0.f;

    STAGE_LOAD(0, 0,   g_Wh, g_Xh, m0, n0, KDIM, KDIM);
    STAGE_LOAD(1, KC2, g_Wh, g_Xh, m0, n0, KDIM, KDIM);
    int sComp = 0, sLoad = 2;
    PIPE_LOOP(g_Wh, g_Xh, m0, n0, KDIM, KDIM);

    // fragment-order store (+bias)
    float4* zf = (float4*)(g_zxF + (((size_t)t * 20 + blockIdx.x) * 32 + btile) * 16384);
    const int rbase = m0 + wm * 64 + (lane >> 2);
    #pragma unroll
    for (int mt = 0; mt < 4; mt++) {
        int row = rbase + mt * 16;
        float br0 = g_bias2560[row];
        float br8 = g_bias2560[row + 8];
        #pragma unroll
        for (int nt = 0; nt < 4; nt++) {
            float4 v = make_float4(acc[mt][nt][0] + br0, acc[mt][nt][1] + br0,
                                   acc[mt][nt][2] + br8, acc[mt][nt][3] + br8);
            zf[(mt * 4 + nt) * 256 + tid] = v;
        }
    }
}

// ---------------- per-step recurrent GEMM (m=rows, n=batch) ---------------------
__global__ __launch_bounds__(256, 2)
void step_kernel(int t) {
    extern __shared__ char sm[];
    const uint32_t smb = smem_u32(sm);
    const int tid  = threadIdx.x;
    const int lane = tid & 31;
    const int wid  = tid >> 5;
    const int wm   = wid & 1;
    const int wn   = wid >> 1;
    const int mtl   = blockIdx.x;
    const int btile = blockIdx.y;
    const int d     = blockIdx.z;
    const int m0r   = mtl * 128;
    const int n0b   = btile * 128;
    const int p     = t & 1;
    const int q     = 1 - p;

    const __half* WhB = g_WHh + (size_t)d * NDR * KH;
    const __half* HhB = g_Hh + (size_t)(p * 2 + d) * BSZ * KH;

    LANE_OFFSETS();

    STAGE_LOAD(0, 0,   WhB, HhB, m0r, n0b, KH, KH);
    STAGE_LOAD(1, KC2, WhB, HhB, m0r, n0b, KH, KH);

    // init acc from fragment-order zx (overlaps with cp.async staging)
    float acc[4][4][4];
    {
        const float4* zf = (const float4*)(g_zxF +
            (((size_t)t * 20 + (d * 10 + mtl)) * 32 + btile) * 16384);
        #pragma unroll
        for (int mt = 0; mt < 4; mt++)
            #pragma unroll
            for (int nt = 0; nt < 4; nt++) {
                float4 v = zf[(mt * 4 + nt) * 256 + tid];
                acc[mt][nt][0] = v.x; acc[mt][nt][1] = v.y;
                acc[mt][nt][2] = v.z; acc[mt][nt][3] = v.w;
            }
    }

    int sComp = 0, sLoad = 2;
    PIPE_LOOP(WhB, HhB, m0r, n0b, KH, KH);
    __syncthreads();   // all ldmatrix of final chunk done before smem reuse

    // ---- epilogue: 4-lane fragment transpose -> gates -> c update -> hT ----
    const int g = (lane >> 2) & 3;
    float* cS = g_cF + ((size_t)(d * 10 + mtl) * 32 + btile) * 4096;
    float* hT = (float*)sm;   // [128 batch][33]

    #pragma unroll
    for (int mt = 0; mt < 4; mt++) {
        #pragma unroll
        for (int nt = 0; nt < 4; nt++) {
            float v0 = acc[mt][nt][0], v1 = acc[mt][nt][1];
            float v2 = acc[mt][nt][2], v3 = acc[mt][nt][3];
            float a = (g & 2) ? v0 : v2;
            float b = (g & 2) ? v1 : v3;
            a = __shfl_xor_sync(0xffffffffu, a, 8);
            b = __shfl_xor_sync(0xffffffffu, b, 8);
            if (g & 2) { v0 = a; v1 = b; } else { v2 = a; v3 = b; }
            float c01 = (g & 1) ? v0 : v1;
            c01 = __shfl_xor_sync(0xffffffffu, c01, 4);
            if (g & 1) v0 = c01; else v1 = c01;
            float c23 = (g & 1) ? v2 : v3;
            c23 = __shfl_xor_sync(0xffffffffu, c23, 4);
            if (g & 1) v2 = c23; else v3 = c23;
            size_t ci = (size_t)(mt * 4 + nt) * 256 + tid;
            float co = cS[ci];
            float cn = fsig(v1) * co + fsig(v0) * ftanh_(v2);
            cS[ci] = cn;
            float h = fsig(v3) * ftanh_(cn);
            int U = wm * 16 + mt * 4 + ((lane >> 4) & 1) + 2 * (g >> 1);
            int N = wn * 32 + nt * 8 + (lane & 3) * 2 + (g & 1);
            hT[N * 33 + U] = h;
        }
    }
    __syncthreads();

    __half* HhO = g_Hh + (size_t)(q * 2 + d) * BSZ * KH;
    const int U0 = mtl * 32;
    for (int i = tid; i < 128 * 32; i += 256) {
        int bl = i >> 5, ul = i & 31;
        float h = hT[bl * 33 + ul];
        int b = n0b + bl;
        int u = U0 + ul;
        __half hh = __float2half(h);
        HhO[(size_t)b * KH + u] = hh;
        g_hs2[((size_t)b * TT + t) * (2 * KH) + d * KH + u] = hh;
    }
}

// ---------------- attention + FC epilogue ---------------------------------------
#define ATT_SMEM 119856

__global__ __launch_bounds__(256, 1)
void attn_kernel(const float* __restrict__ conv_w,
                 const float* __restrict__ fc_w,
                 const float* __restrict__ fc_b,
                 float* __restrict__ out) {
    extern __shared__ char smem[];
    float* fcT   = (float*)smem;
    float* hstar = (float*)(smem + 96000);
    float* cw    = (float*)(smem + 115200);
    float* e_sh  = cw + 300;
    float* l_sh  = e_sh + 704;
    float* p_sh  = l_sh + 80;

    const int tid = threadIdx.x;
    const int b0  = blockIdx.x * 16;

    for (int i = tid; i < 300; i += 256) cw[i] = conv_w[i];
    for (int i = tid; i < 300 * NCLS; i += 256) {
        int u = i / NCLS, cls = i - u * NCLS;
        fcT[i] = fc_w[(size_t)cls * 300 + u];
    }
    __syncthreads();

    {
        int wid = tid >> 5, lane = tid & 31;
        for (int task = wid; task < 16 * TT; task += 8) {
            int b = task / TT, t = task - b * TT;
            const __half* hp = g_hs2 + ((size_t)(b0 + b) * TT + t) * (2 * KH);
            float s = 0.f;
            for (int u = lane; u < 300; u += 32)
                s += ftanh_(__half2float(hp[u]) + __half2float(hp[KH + u])) * cw[u];
            #pragma unroll
            for (int o = 16; o > 0; o >>= 1) s += __shfl_xor_sync(0xffffffffu, s, o);
            if (lane == 0) e_sh[b * 44 + t] = s;
        }
    }
    __syncthreads();

    if (tid < 16) {
        float m = -1e30f;
        for (int t = 0; t < TT; t++) m = fmaxf(m, e_sh[tid * 44 + t]);
        float ss = 0.f;
        for (int t = 0; t < TT; t++) { float pz = __expf(e_sh[tid * 44 + t] - m); e_sh[tid * 44 + t] = pz; ss += pz; }
        float inv = 1.0f / ss;
        for (int t = 0; t < TT; t++) e_sh[tid * 44 + t] *= inv;
    }
    __syncthreads();

    for (int i = tid; i < 16 * 300; i += 256) {
        int b = i / 300, u = i - b * 300;
        const __half* hp = g_hs2 + ((size_t)(b0 + b) * TT) * (2 * KH) + u;
        float acc = 0.f;
        for (int t = 0; t < TT; t++)
            acc += (__half2float(hp[(size_t)t * (2 * KH)]) +
                    __half2float(hp[(size_t)t * (2 * KH) + KH])) * e_sh[b * 44 + t];
        hstar[i] = ftanh_(acc);
    }
    __syncthreads();

    for (int b = 0; b < 16; b++) {
        if (tid < NCLS) {
            float acc = fc_b[tid];
            const float* hv = hstar + b * 300;
            for (int u = 0; u < 300; u++) acc += hv[u] * fcT[u * NCLS + tid];
            l_sh[tid] = acc;
        }
        __syncthreads();
        if (tid < NCLS) {
            float m = -1e30f;
            for (int j = 0; j < NCLS; j++) m = fmaxf(m, l_sh[j]);
            p_sh[tid] = __expf(l_sh[tid] - m);
        }
        __syncthreads();
        if (tid < NCLS) {
            float s = 0.f;
            for (int j = 0; j < NCLS; j++) s += p_sh[j];
            out[(size_t)(b0 + b) * NCLS + tid] = p_sh[tid] / s;
        }
        __syncthreads();
    }
}

// ---------------- launch ---------------------------------------------------------
extern "C" void kernel_launch(void* const* d_in, const int* in_sizes, int n_in,
                              void* d_out, int out_size) {
    const float* x      = (const float*)d_in[0];
    const float* w_ih   = (const float*)d_in[1];
    const float* w_hh   = (const float*)d_in[2];
    const float* b_ih   = (const float*)d_in[3];
    const float* b_hh   = (const float*)d_in[4];
    const float* conv_w = (const float*)d_in[5];
    const float* fc_w   = (const float*)d_in[6];
    const float* fc_b   = (const float*)d_in[7];
    float* out = (float*)d_out;

    cudaFuncSetAttribute(gemm_zx_kernel,     cudaFuncAttributeMaxDynamicSharedMemorySize, GS_BYTES);
    cudaFuncSetAttribute(step_kernel,        cudaFuncAttributeMaxDynamicSharedMemorySize, GS_BYTES);
    cudaFuncSetAttribute(attn_kernel,        cudaFuncAttributeMaxDynamicSharedMemorySize, ATT_SMEM);
    cudaFuncSetAttribute(prep_xsplit_kernel, cudaFuncAttributeMaxDynamicSharedMemorySize, XS_BYTES);

    cudaStream_t sB;
    cudaStreamCreateWithFlags(&sB, cudaStreamNonBlocking);
    cudaEvent_t evFork, evZx[TT];
    cudaEventCreateWithFlags(&evFork, cudaEventDisableTiming);
    for (int t = 0; t < TT; t++) cudaEventCreateWithFlags(&evZx[t], cudaEventDisableTiming);

    // zx-side preps on the main (captured origin) stream
    prep_wsplit_kernel<<<(MROWS * KDIM + 255) / 256, 256>>>(w_ih);
    prep_xsplit_kernel<<<BSZ, 256, XS_BYTES>>>(x);
    prep_bias_kernel<<<(MROWS + 255) / 256, 256>>>(b_ih, b_hh);

    // fork: zx per-t launches on sB
    cudaEventRecord(evFork, 0);
    cudaStreamWaitEvent(sB, evFork, 0);
    for (int t = 0; t < TT; t++) {
        gemm_zx_kernel<<<dim3(MTILES, 32), 256, GS_BYTES, sB>>>(t);
        cudaEventRecord(evZx[t], sB);
    }

    // step-side preps on the main stream (overlap with early zx work)
    prep_whhsplit_kernel<<<(2 * NDR * KH + 255) / 256, 256>>>(w_hh);
    zero_state_kernel<<<(int)(((size_t)2 * BSZ * KH + 255) / 256), 256>>>();

    // recurrence: step t gated on zx_t
    for (int t = 0; t < TT; t++) {
        cudaStreamWaitEvent(0, evZx[t], 0);
        step_kernel<<<dim3(10, 32, 2), 256, GS_BYTES>>>(t);
    }

    attn_kernel<<<BSZ / 16, 256, ATT_SMEM>>>(conv_w, fc_w, fc_b, out);
}